// round 1
// baseline (speedup 1.0000x reference)
#include <cuda_runtime.h>
#include <math.h>
#include <stdint.h>

#define L 4096
#define HID 2048
#define HK 16
#define HV 32
#define DK 128
#define DV 128
#define KEY_DIM 2048
#define VALUE_DIM 4096
#define NQKVZ 12288
#define CONV_DIM 8192
#define EPS 1e-6f
#define CT 32   // scan chunk (timesteps staged in smem)

// ---------------- scratch (static device globals; no allocs allowed) ----------------
__device__ float g_qkvz[(size_t)L * NQKVZ];    // 201 MB
__device__ float g_ba[(size_t)L * 64];
__device__ float g_mixed[(size_t)L * CONV_DIM]; // 128 MB (q|k|v post-conv; q,k normalized in place)
__device__ float g_g[(size_t)L * HV];
__device__ float g_beta[(size_t)L * HV];
__device__ float g_core[(size_t)L * VALUE_DIM]; // 64 MB

// ---------------- generic fp32 SGEMM: C = A @ B  (row-major) ----------------
// BM=128, BN=128, BK=16, 256 threads, 8x8 per thread, float4 loads.
// Asel: 0 = external A, 1 = g_core. Csel: 0 = external C, 1 = g_qkvz, 2 = g_ba.
__global__ void __launch_bounds__(256) sgemm_kernel(
    const float* __restrict__ A_ext, const float* __restrict__ B,
    float* __restrict__ C_ext, int M, int N, int K, int Asel, int Csel)
{
    const float* A = (Asel == 0) ? A_ext : g_core;
    float* C = (Csel == 0) ? C_ext : ((Csel == 1) ? g_qkvz : g_ba);

    __shared__ float As[16][128];
    __shared__ float Bs[16][128];

    const int tid = threadIdx.x;
    const int mBase = blockIdx.y * 128;
    const int nBase = blockIdx.x * 128;
    const int tx = (tid & 15) * 8;      // col within tile
    const int ty = (tid >> 4) * 8;      // row within tile
    const int aRow = tid >> 2;          // 0..63 (+64)
    const int aCol = (tid & 3) << 2;    // 0,4,8,12
    const int bRow = tid >> 5;          // 0..7 (+8)
    const int bCol = (tid & 31) << 2;   // 0..124

    float acc[8][8];
#pragma unroll
    for (int i = 0; i < 8; i++)
#pragma unroll
        for (int j = 0; j < 8; j++) acc[i][j] = 0.f;

    for (int k0 = 0; k0 < K; k0 += 16) {
#pragma unroll
        for (int r = 0; r < 2; r++) {
            int row = aRow + r * 64;
            float4 v = make_float4(0.f, 0.f, 0.f, 0.f);
            if (mBase + row < M)
                v = *reinterpret_cast<const float4*>(A + (size_t)(mBase + row) * K + k0 + aCol);
            As[aCol + 0][row] = v.x;
            As[aCol + 1][row] = v.y;
            As[aCol + 2][row] = v.z;
            As[aCol + 3][row] = v.w;
        }
#pragma unroll
        for (int r = 0; r < 2; r++) {
            int row = bRow + r * 8;
            float4 v = make_float4(0.f, 0.f, 0.f, 0.f);
            if (nBase + bCol < N)
                v = *reinterpret_cast<const float4*>(B + (size_t)(k0 + row) * N + nBase + bCol);
            *reinterpret_cast<float4*>(&Bs[row][bCol]) = v;
        }
        __syncthreads();

#pragma unroll
        for (int kk = 0; kk < 16; kk++) {
            float ra[8], rb[8];
            *reinterpret_cast<float4*>(&ra[0]) = *reinterpret_cast<const float4*>(&As[kk][ty]);
            *reinterpret_cast<float4*>(&ra[4]) = *reinterpret_cast<const float4*>(&As[kk][ty + 4]);
            *reinterpret_cast<float4*>(&rb[0]) = *reinterpret_cast<const float4*>(&Bs[kk][tx]);
            *reinterpret_cast<float4*>(&rb[4]) = *reinterpret_cast<const float4*>(&Bs[kk][tx + 4]);
#pragma unroll
            for (int i = 0; i < 8; i++)
#pragma unroll
                for (int j = 0; j < 8; j++)
                    acc[i][j] = fmaf(ra[i], rb[j], acc[i][j]);
        }
        __syncthreads();
    }

#pragma unroll
    for (int i = 0; i < 8; i++) {
        int row = mBase + ty + i;
        if (row >= M) break;
#pragma unroll
        for (int j = 0; j < 8; j += 4) {
            int col = nBase + tx + j;
            if (col + 3 < N) {
                float4 v = make_float4(acc[i][j], acc[i][j + 1], acc[i][j + 2], acc[i][j + 3]);
                *reinterpret_cast<float4*>(C + (size_t)row * N + col) = v;
            } else {
                for (int jj = 0; jj < 4; jj++)
                    if (col + jj < N) C[(size_t)row * N + col + jj] = acc[i][j + jj];
            }
        }
    }
}

// ---------------- conv (causal depthwise K=4) + silu, with qkvz->mixed column gather ----------------
__device__ __forceinline__ int mixed_src_col(int c) {
    if (c < KEY_DIM) { int h = c >> 7, d = c & 127; return h * 768 + d; }
    if (c < 2 * KEY_DIM) { int cc = c - KEY_DIM; int h = cc >> 7, d = cc & 127; return h * 768 + 128 + d; }
    int cc = c - 2 * KEY_DIM; int hv = cc >> 7, d = cc & 127; int h = hv >> 1;
    return h * 768 + 256 + (hv & 1) * 128 + d;
}

__global__ void conv_silu_kernel(const float* __restrict__ conv_w) {
    int idx = blockIdx.x * blockDim.x + threadIdx.x;
    if (idx >= L * CONV_DIM) return;
    int l = idx / CONV_DIM;
    int c = idx - l * CONV_DIM;
    int src = mixed_src_col(c);
    float w0 = conv_w[c * 4 + 0], w1 = conv_w[c * 4 + 1];
    float w2 = conv_w[c * 4 + 2], w3 = conv_w[c * 4 + 3];
    float acc = g_qkvz[(size_t)l * NQKVZ + src] * w3;              // x[l]   * w[3]
    if (l >= 1) acc += g_qkvz[(size_t)(l - 1) * NQKVZ + src] * w2; // x[l-1] * w[2]
    if (l >= 2) acc += g_qkvz[(size_t)(l - 2) * NQKVZ + src] * w1;
    if (l >= 3) acc += g_qkvz[(size_t)(l - 3) * NQKVZ + src] * w0;
    g_mixed[(size_t)idx] = acc / (1.f + expf(-acc));               // silu
}

// ---------------- l2norm of q and k (in place), q additionally * DK^-0.5 ----------------
__global__ void qknorm_kernel() {
    int b = blockIdx.x;          // L*HK blocks
    int l = b >> 4, h = b & 15;
    int d = threadIdx.x;         // 128
    float* qp = g_mixed + (size_t)l * CONV_DIM + h * DK + d;
    float* kp = qp + KEY_DIM;
    float q = *qp, k = *kp;
    float sq = q * q, sk = k * k;
#pragma unroll
    for (int off = 16; off; off >>= 1) {
        sq += __shfl_xor_sync(0xffffffffu, sq, off);
        sk += __shfl_xor_sync(0xffffffffu, sk, off);
    }
    __shared__ float ssq[4], ssk[4];
    int w = d >> 5;
    if ((d & 31) == 0) { ssq[w] = sq; ssk[w] = sk; }
    __syncthreads();
    sq = ssq[0] + ssq[1] + ssq[2] + ssq[3];
    sk = ssk[0] + ssk[1] + ssk[2] + ssk[3];
    *qp = q * rsqrtf(sq + EPS) * 0.08838834764831845f; // * DK^-0.5
    *kp = k * rsqrtf(sk + EPS);
}

// ---------------- gate/decay: g = -exp(A_log)*softplus(a+dt_bias), beta = sigmoid(b) ----------------
__global__ void gbeta_kernel(const float* __restrict__ A_log, const float* __restrict__ dt_bias) {
    int idx = blockIdx.x * blockDim.x + threadIdx.x;
    if (idx >= L * HV) return;
    int l = idx >> 5, hv = idx & 31;
    int hk = hv >> 1, r = hv & 1;
    float b = g_ba[l * 64 + hk * 4 + r];
    float a = g_ba[l * 64 + hk * 4 + 2 + r];
    float x = a + dt_bias[hv];
    float sp = (x > 20.f) ? x : log1pf(expf(x));
    g_g[idx] = -expf(A_log[hv]) * sp;
    g_beta[idx] = 1.f / (1.f + expf(-b));
}

// ---------------- delta-rule scan: warp-per-(head,dv)-column ----------------
// State S[:, (hv,dv)] is 128 floats: 4 regs/lane, dk = 32*j + lane.
__global__ void __launch_bounds__(256) scan_kernel() {
    __shared__ float k_s[CT][DK];
    __shared__ float q_s[CT][DK];
    __shared__ float e_s[CT], b_s[CT];
    __shared__ float v_s[CT][8];
    __shared__ float o_s[CT][8];

    const int bx = blockIdx.x;           // 512 = HV * (DV/8)
    const int hv = bx >> 4;
    const int dvb = (bx & 15) << 3;
    const int hk = hv >> 1;
    const int tid = threadIdx.x;
    const int w = tid >> 5, lane = tid & 31;

    float S0 = 0.f, S1 = 0.f, S2 = 0.f, S3 = 0.f;

    for (int t0 = 0; t0 < L; t0 += CT) {
        // stage chunk into smem
#pragma unroll
        for (int i = 0; i < CT * DK / 256; i++) {   // 16 iters
            int e = tid + i * 256;
            int t = e >> 7, d = e & 127;
            size_t row = (size_t)(t0 + t) * CONV_DIM;
            q_s[t][d] = g_mixed[row + hk * DK + d];
            k_s[t][d] = g_mixed[row + KEY_DIM + hk * DK + d];
        }
        {
            int t = tid >> 3, j = tid & 7;          // 256 = 32*8 exactly
            v_s[t][j] = g_mixed[(size_t)(t0 + t) * CONV_DIM + 2 * KEY_DIM + hv * DV + dvb + j];
        }
        if (tid < CT) {
            e_s[tid] = expf(g_g[(t0 + tid) * HV + hv]);
            b_s[tid] = g_beta[(t0 + tid) * HV + hv];
        }
        __syncthreads();

        for (int t = 0; t < CT; t++) {
            float e = e_s[t];
            S0 *= e; S1 *= e; S2 *= e; S3 *= e;
            float k0 = k_s[t][lane], k1 = k_s[t][lane + 32];
            float k2 = k_s[t][lane + 64], k3 = k_s[t][lane + 96];
            float kv = fmaf(S3, k3, fmaf(S2, k2, fmaf(S1, k1, S0 * k0)));
#pragma unroll
            for (int off = 16; off; off >>= 1) kv += __shfl_xor_sync(0xffffffffu, kv, off);
            float delta = (v_s[t][w] - kv) * b_s[t];
            S0 = fmaf(k0, delta, S0);
            S1 = fmaf(k1, delta, S1);
            S2 = fmaf(k2, delta, S2);
            S3 = fmaf(k3, delta, S3);
            float q0 = q_s[t][lane], q1 = q_s[t][lane + 32];
            float q2 = q_s[t][lane + 64], q3 = q_s[t][lane + 96];
            float o = fmaf(S3, q3, fmaf(S2, q2, fmaf(S1, q1, S0 * q0)));
#pragma unroll
            for (int off = 16; off; off >>= 1) o += __shfl_xor_sync(0xffffffffu, o, off);
            if (lane == 0) o_s[t][w] = o;
        }
        __syncthreads();
        {
            int t = tid >> 3, j = tid & 7;
            g_core[(size_t)(t0 + t) * VALUE_DIM + hv * DV + dvb + j] = o_s[t][j];
        }
        // o_s is re-written only after the sync at the top of the next chunk's step loop
    }
}

// ---------------- output RMS-norm * norm_weight * silu(z), in place on g_core ----------------
__global__ void gate_kernel(const float* __restrict__ norm_weight) {
    int b = blockIdx.x;           // L*HV blocks
    int l = b >> 5, hv = b & 31;
    int d = threadIdx.x;          // 128
    size_t ci = (size_t)l * VALUE_DIM + hv * DV + d;
    float c = g_core[ci];
    float s = c * c;
#pragma unroll
    for (int off = 16; off; off >>= 1) s += __shfl_xor_sync(0xffffffffu, s, off);
    __shared__ float sm[4];
    if ((d & 31) == 0) sm[d >> 5] = s;
    __syncthreads();
    s = sm[0] + sm[1] + sm[2] + sm[3];
    float scale = rsqrtf(s * (1.f / 128.f) + EPS);
    int hk = hv >> 1, r = hv & 1;
    float z = g_qkvz[(size_t)l * NQKVZ + hk * 768 + 512 + r * 128 + d];
    float sz = z / (1.f + expf(-z));
    g_core[ci] = c * scale * norm_weight[d] * sz;
}

// ---------------- launch ----------------
extern "C" void kernel_launch(void* const* d_in, const int* in_sizes, int n_in,
                              void* d_out, int out_size) {
    const float* hs      = (const float*)d_in[0];
    const float* W_qkvz  = (const float*)d_in[1];
    const float* W_ba    = (const float*)d_in[2];
    const float* conv_w  = (const float*)d_in[3];
    const float* A_log   = (const float*)d_in[4];
    const float* dt_bias = (const float*)d_in[5];
    const float* norm_w  = (const float*)d_in[6];
    const float* W_out   = (const float*)d_in[7];
    float* out = (float*)d_out;

    // 1) qkvz = hs @ W_qkvz  -> g_qkvz
    {
        dim3 grid(NQKVZ / 128, L / 128);
        sgemm_kernel<<<grid, 256>>>(hs, W_qkvz, nullptr, L, NQKVZ, HID, 0, 1);
    }
    // 2) ba = hs @ W_ba -> g_ba
    {
        dim3 grid(1, L / 128);
        sgemm_kernel<<<grid, 256>>>(hs, W_ba, nullptr, L, 64, HID, 0, 2);
    }
    // 3) conv + silu -> g_mixed
    conv_silu_kernel<<<(L * CONV_DIM) / 256, 256>>>(conv_w);
    // 4) q/k l2norm in place
    qknorm_kernel<<<L * HK, 128>>>();
    // 5) g, beta
    gbeta_kernel<<<(L * HV + 255) / 256, 256>>>(A_log, dt_bias);
    // 6) delta-rule scan -> g_core
    scan_kernel<<<HV * (DV / 8), 256>>>();
    // 7) RMS norm + silu(z) gating in place
    gate_kernel<<<L * HV, 128>>>(norm_w);
    // 8) out = core @ W_out
    {
        dim3 grid(HID / 128, L / 128);
        sgemm_kernel<<<grid, 256>>>(nullptr, W_out, out, L, HID, VALUE_DIM, 1, 0);
    }
}

// round 4
// speedup vs baseline: 1.7465x; 1.7465x over previous
#include <cuda_runtime.h>
#include <cuda_bf16.h>
#include <math.h>
#include <stdint.h>

#define L 4096
#define HID 2048
#define HK 16
#define HV 32
#define DK 128
#define DV 128
#define KEY_DIM 2048
#define VALUE_DIM 4096
#define NQKVZ 12288
#define CONV_DIM 8192
#define EPS 1e-6f
#define CT 32

// ================= scratch (device globals; allocs forbidden) =================
__device__ float g_qkvz[(size_t)L * NQKVZ];
__device__ float g_ba[(size_t)L * 64];
__device__ float g_mixed[(size_t)L * CONV_DIM];
__device__ float g_g[(size_t)L * HV];
__device__ float g_beta[(size_t)L * HV];
__device__ float g_core[(size_t)L * VALUE_DIM];

__device__ __nv_bfloat16 g_A1hi[(size_t)L * HID];
__device__ __nv_bfloat16 g_A1lo[(size_t)L * HID];
__device__ __nv_bfloat16 g_B1hi[(size_t)NQKVZ * HID];   // W_qkvz^T  [N][K]
__device__ __nv_bfloat16 g_B1lo[(size_t)NQKVZ * HID];
__device__ __nv_bfloat16 g_A3hi[(size_t)L * VALUE_DIM]; // gated core
__device__ __nv_bfloat16 g_A3lo[(size_t)L * VALUE_DIM];
__device__ __nv_bfloat16 g_B3hi[(size_t)HID * VALUE_DIM]; // W_out^T  [N][K]
__device__ __nv_bfloat16 g_B3lo[(size_t)HID * VALUE_DIM];

// ================= helpers =================
__device__ __forceinline__ uint32_t smem_u32(const void* p) {
    uint32_t a;
    asm("{ .reg .u64 t; cvta.to.shared.u64 t, %1; cvt.u32.u64 %0, t; }" : "=r"(a) : "l"(p));
    return a;
}

__device__ __forceinline__ void ldsm_x4(uint32_t* r, uint32_t addr) {
    asm volatile("ldmatrix.sync.aligned.m8n8.x4.shared.b16 {%0,%1,%2,%3}, [%4];"
                 : "=r"(r[0]), "=r"(r[1]), "=r"(r[2]), "=r"(r[3]) : "r"(addr));
}

__device__ __forceinline__ void mma16816(float* c, const uint32_t* a, uint32_t b0, uint32_t b1) {
    asm volatile(
        "mma.sync.aligned.m16n8k16.row.col.f32.bf16.bf16.f32 "
        "{%0,%1,%2,%3}, {%4,%5,%6,%7}, {%8,%9}, {%0,%1,%2,%3};"
        : "+f"(c[0]), "+f"(c[1]), "+f"(c[2]), "+f"(c[3])
        : "r"(a[0]), "r"(a[1]), "r"(a[2]), "r"(a[3]), "r"(b0), "r"(b1));
}

// ================= HMMA bf16x3 GEMM: C = A @ B^T_stored =================
// A*, B* bf16 [rows][Ktot] K-major. Tile 128(M) x 128(N), BK=32.
// smem rows: 128 bytes = [32 hi bf16 | 32 lo bf16], 16B-atom XOR swizzle.
__global__ void __launch_bounds__(256, 2) gemm3x(int which, float* __restrict__ Cext,
                                                 int Ntot, int Ktot)
{
    const __nv_bfloat16 *Ahi, *Alo, *Bhi, *Blo;
    float* C;
    if (which == 0) { Ahi = g_A1hi; Alo = g_A1lo; Bhi = g_B1hi; Blo = g_B1lo; C = g_qkvz; }
    else            { Ahi = g_A3hi; Alo = g_A3lo; Bhi = g_B3hi; Blo = g_B3lo; C = Cext; }

    __shared__ __align__(1024) char sA[128 * 128];
    __shared__ __align__(1024) char sB[128 * 128];

    const int tid = threadIdx.x;
    const int wid = tid >> 5;
    const int lane = tid & 31;
    const int wm = wid & 1;        // 2 warps along M -> 64 rows each
    const int wn = wid >> 1;       // 4 warps along N -> 32 cols each
    const size_t m0 = (size_t)blockIdx.y * 128;
    const size_t n0 = (size_t)blockIdx.x * 128;

    const uint32_t sAu = smem_u32(sA);
    const uint32_t sBu = smem_u32(sB);

    // ldmatrix per-lane geometry: row_in_tile = lane & 15, k-half = lane >> 4
    const int lrow = lane & 15;
    const uint32_t kadd = (uint32_t)(lane >> 4) << 4;   // 0 or 16 bytes

    float acc[4][4][4];
#pragma unroll
    for (int i = 0; i < 4; i++)
#pragma unroll
        for (int j = 0; j < 4; j++)
#pragma unroll
            for (int r = 0; r < 4; r++) acc[i][j][r] = 0.f;

    const int nch = Ktot >> 5;
    for (int c = 0; c < nch; c++) {
        const int k0 = c << 5;
        // ---- stage A and B panels (each: 128 rows x 128B) ----
#pragma unroll
        for (int i = 0; i < 4; i++) {
            int u = tid + i * 256;
            int row = u >> 3, ch = u & 7;
            int half = ch >> 2;            // 0 hi, 1 lo
            int kc = (ch & 3) * 8;         // element offset
            uint32_t dst = (uint32_t)(row * 128 + (((uint32_t)(ch * 16)) ^ (((uint32_t)row & 7) << 4)));
            const __nv_bfloat16* srcA = (half ? Alo : Ahi) + (m0 + row) * (size_t)Ktot + k0 + kc;
            const __nv_bfloat16* srcB = (half ? Blo : Bhi) + (n0 + row) * (size_t)Ktot + k0 + kc;
            *(uint4*)(sA + dst) = *(const uint4*)srcA;
            *(uint4*)(sB + dst) = *(const uint4*)srcB;
        }
        __syncthreads();

        // ---- compute ----
#pragma unroll
        for (int ks = 0; ks < 2; ks++) {
            uint32_t ah[4][4], al[4][4], bh[2][4], bl[2][4];
            const uint32_t koffh = (uint32_t)(ks * 32) + kadd;        // hi bytes
            const uint32_t koffl = 64u + (uint32_t)(ks * 32) + kadd;  // lo bytes
#pragma unroll
            for (int i = 0; i < 4; i++) {
                int row = wm * 64 + i * 16 + lrow;
                uint32_t ro = (uint32_t)(row * 128);
                uint32_t rx = ((uint32_t)row & 7) << 4;
                ldsm_x4(ah[i], sAu + ro + (koffh ^ rx));
                ldsm_x4(al[i], sAu + ro + (koffl ^ rx));
            }
#pragma unroll
            for (int j2 = 0; j2 < 2; j2++) {
                int row = wn * 32 + j2 * 16 + lrow;
                uint32_t ro = (uint32_t)(row * 128);
                uint32_t rx = ((uint32_t)row & 7) << 4;
                ldsm_x4(bh[j2], sBu + ro + (koffh ^ rx));
                ldsm_x4(bl[j2], sBu + ro + (koffl ^ rx));
            }
#pragma unroll
            for (int i = 0; i < 4; i++) {
#pragma unroll
                for (int j = 0; j < 4; j++) {
                    int j2 = j >> 1, jo = j & 1;
                    uint32_t bh0 = bh[j2][jo], bh1 = bh[j2][2 + jo];
                    uint32_t bl0 = bl[j2][jo], bl1 = bl[j2][2 + jo];
                    mma16816(acc[i][j], ah[i], bh0, bh1);
                    mma16816(acc[i][j], al[i], bh0, bh1);
                    mma16816(acc[i][j], ah[i], bl0, bl1);
                }
            }
        }
        __syncthreads();
    }

    // ---- epilogue: direct fp32 stores ----
#pragma unroll
    for (int i = 0; i < 4; i++) {
        size_t row = m0 + wm * 64 + i * 16 + (lane >> 2);
#pragma unroll
        for (int j = 0; j < 4; j++) {
            size_t col = n0 + wn * 32 + j * 8 + (lane & 3) * 2;
            *(float2*)(C + row * (size_t)Ntot + col) = make_float2(acc[i][j][0], acc[i][j][1]);
            *(float2*)(C + (row + 8) * (size_t)Ntot + col) = make_float2(acc[i][j][2], acc[i][j][3]);
        }
    }
}

// ================= split / transpose-split conversions =================
__global__ void split_hs(const float* __restrict__ x, int n) {
    int i = blockIdx.x * blockDim.x + threadIdx.x;
    if (i >= n) return;
    float v = x[i];
    __nv_bfloat16 h = __float2bfloat16(v);
    g_A1hi[i] = h;
    g_A1lo[i] = __float2bfloat16(v - __bfloat162float(h));
}

// W [K][N] row-major -> T [N][K] bf16 hi/lo. which: 0 -> B1 (W_qkvz), 1 -> B3 (W_out)
__global__ void transpose_split(const float* __restrict__ W, int K, int N, int which) {
    __shared__ float t[32][33];
    __nv_bfloat16* Thi = which == 0 ? g_B1hi : g_B3hi;
    __nv_bfloat16* Tlo = which == 0 ? g_B1lo : g_B3lo;
    int n0 = blockIdx.x * 32, k0 = blockIdx.y * 32;
    int tx = threadIdx.x, ty = threadIdx.y;   // (32, 8)
#pragma unroll
    for (int i = 0; i < 4; i++)
        t[ty + i * 8][tx] = W[(size_t)(k0 + ty + i * 8) * N + n0 + tx];
    __syncthreads();
#pragma unroll
    for (int i = 0; i < 4; i++) {
        float v = t[tx][ty + i * 8];
        __nv_bfloat16 h = __float2bfloat16(v);
        size_t o = (size_t)(n0 + ty + i * 8) * K + k0 + tx;
        Thi[o] = h;
        Tlo[o] = __float2bfloat16(v - __bfloat162float(h));
    }
}

// ================= small fp32 SGEMM for ba (N=64) =================
__global__ void __launch_bounds__(256) sgemm_ba(const float* __restrict__ A, const float* __restrict__ B,
                                                int M, int N, int K)
{
    float* C = g_ba;
    __shared__ float As[16][128];
    __shared__ float Bs[16][128];
    const int tid = threadIdx.x;
    const int mBase = blockIdx.y * 128;
    const int tx = (tid & 15) * 8;
    const int ty = (tid >> 4) * 8;
    const int aRow = tid >> 2;
    const int aCol = (tid & 3) << 2;
    const int bRow = tid >> 5;
    const int bCol = (tid & 31) << 2;

    float acc[8][8];
#pragma unroll
    for (int i = 0; i < 8; i++)
#pragma unroll
        for (int j = 0; j < 8; j++) acc[i][j] = 0.f;

    for (int k0 = 0; k0 < K; k0 += 16) {
#pragma unroll
        for (int r = 0; r < 2; r++) {
            int row = aRow + r * 64;
            float4 v = *reinterpret_cast<const float4*>(A + (size_t)(mBase + row) * K + k0 + aCol);
            As[aCol + 0][row] = v.x; As[aCol + 1][row] = v.y;
            As[aCol + 2][row] = v.z; As[aCol + 3][row] = v.w;
        }
#pragma unroll
        for (int r = 0; r < 2; r++) {
            int row = bRow + r * 8;
            float4 v = make_float4(0.f, 0.f, 0.f, 0.f);
            if (bCol < N)
                v = *reinterpret_cast<const float4*>(B + (size_t)(k0 + row) * N + bCol);
            *reinterpret_cast<float4*>(&Bs[row][bCol]) = v;
        }
        __syncthreads();
#pragma unroll
        for (int kk = 0; kk < 16; kk++) {
            float ra[8], rb[8];
            *reinterpret_cast<float4*>(&ra[0]) = *reinterpret_cast<const float4*>(&As[kk][ty]);
            *reinterpret_cast<float4*>(&ra[4]) = *reinterpret_cast<const float4*>(&As[kk][ty + 4]);
            *reinterpret_cast<float4*>(&rb[0]) = *reinterpret_cast<const float4*>(&Bs[kk][tx]);
            *reinterpret_cast<float4*>(&rb[4]) = *reinterpret_cast<const float4*>(&Bs[kk][tx + 4]);
#pragma unroll
            for (int i = 0; i < 8; i++)
#pragma unroll
                for (int j = 0; j < 8; j++)
                    acc[i][j] = fmaf(ra[i], rb[j], acc[i][j]);
        }
        __syncthreads();
    }
#pragma unroll
    for (int i = 0; i < 8; i++) {
        int row = mBase + ty + i;
#pragma unroll
        for (int j = 0; j < 8; j++) {
            int col = tx + j;
            if (col < N) C[(size_t)row * N + col] = acc[i][j];
        }
    }
}

// ================= conv + silu =================
__device__ __forceinline__ int mixed_src_col(int c) {
    if (c < KEY_DIM) { int h = c >> 7, d = c & 127; return h * 768 + d; }
    if (c < 2 * KEY_DIM) { int cc = c - KEY_DIM; int h = cc >> 7, d = cc & 127; return h * 768 + 128 + d; }
    int cc = c - 2 * KEY_DIM; int hv = cc >> 7, d = cc & 127; int h = hv >> 1;
    return h * 768 + 256 + (hv & 1) * 128 + d;
}

__global__ void conv_silu_kernel(const float* __restrict__ conv_w) {
    int idx = blockIdx.x * blockDim.x + threadIdx.x;
    if (idx >= L * CONV_DIM) return;
    int l = idx / CONV_DIM;
    int c = idx - l * CONV_DIM;
    int src = mixed_src_col(c);
    float w0 = conv_w[c * 4 + 0], w1 = conv_w[c * 4 + 1];
    float w2 = conv_w[c * 4 + 2], w3 = conv_w[c * 4 + 3];
    float acc = g_qkvz[(size_t)l * NQKVZ + src] * w3;
    if (l >= 1) acc += g_qkvz[(size_t)(l - 1) * NQKVZ + src] * w2;
    if (l >= 2) acc += g_qkvz[(size_t)(l - 2) * NQKVZ + src] * w1;
    if (l >= 3) acc += g_qkvz[(size_t)(l - 3) * NQKVZ + src] * w0;
    g_mixed[(size_t)idx] = acc / (1.f + expf(-acc));
}

// ================= q/k l2norm =================
__global__ void qknorm_kernel() {
    int b = blockIdx.x;
    int l = b >> 4, h = b & 15;
    int d = threadIdx.x;
    float* qp = g_mixed + (size_t)l * CONV_DIM + h * DK + d;
    float* kp = qp + KEY_DIM;
    float q = *qp, k = *kp;
    float sq = q * q, sk = k * k;
#pragma unroll
    for (int off = 16; off; off >>= 1) {
        sq += __shfl_xor_sync(0xffffffffu, sq, off);
        sk += __shfl_xor_sync(0xffffffffu, sk, off);
    }
    __shared__ float ssq[4], ssk[4];
    int w = d >> 5;
    if ((d & 31) == 0) { ssq[w] = sq; ssk[w] = sk; }
    __syncthreads();
    sq = ssq[0] + ssq[1] + ssq[2] + ssq[3];
    sk = ssk[0] + ssk[1] + ssk[2] + ssk[3];
    *qp = q * rsqrtf(sq + EPS) * 0.08838834764831845f;
    *kp = k * rsqrtf(sk + EPS);
}

// ================= g, beta =================
__global__ void gbeta_kernel(const float* __restrict__ A_log, const float* __restrict__ dt_bias) {
    int idx = blockIdx.x * blockDim.x + threadIdx.x;
    if (idx >= L * HV) return;
    int l = idx >> 5, hv = idx & 31;
    int hk = hv >> 1, r = hv & 1;
    float b = g_ba[l * 64 + hk * 4 + r];
    float a = g_ba[l * 64 + hk * 4 + 2 + r];
    float x = a + dt_bias[hv];
    float sp = (x > 20.f) ? x : log1pf(expf(x));
    g_g[idx] = -expf(A_log[hv]) * sp;
    g_beta[idx] = 1.f / (1.f + expf(-b));
}

// ================= delta-rule scan =================
__global__ void __launch_bounds__(256) scan_kernel() {
    __shared__ float k_s[CT][DK];
    __shared__ float q_s[CT][DK];
    __shared__ float e_s[CT], b_s[CT];
    __shared__ float v_s[CT][8];
    __shared__ float o_s[CT][8];

    const int bx = blockIdx.x;
    const int hv = bx >> 4;
    const int dvb = (bx & 15) << 3;
    const int hk = hv >> 1;
    const int tid = threadIdx.x;
    const int w = tid >> 5, lane = tid & 31;

    float S0 = 0.f, S1 = 0.f, S2 = 0.f, S3 = 0.f;

    for (int t0 = 0; t0 < L; t0 += CT) {
#pragma unroll
        for (int i = 0; i < CT * DK / 256; i++) {
            int e = tid + i * 256;
            int t = e >> 7, d = e & 127;
            size_t row = (size_t)(t0 + t) * CONV_DIM;
            q_s[t][d] = g_mixed[row + hk * DK + d];
            k_s[t][d] = g_mixed[row + KEY_DIM + hk * DK + d];
        }
        {
            int t = tid >> 3, j = tid & 7;
            v_s[t][j] = g_mixed[(size_t)(t0 + t) * CONV_DIM + 2 * KEY_DIM + hv * DV + dvb + j];
        }
        if (tid < CT) {
            e_s[tid] = expf(g_g[(t0 + tid) * HV + hv]);
            b_s[tid] = g_beta[(t0 + tid) * HV + hv];
        }
        __syncthreads();

        for (int t = 0; t < CT; t++) {
            float e = e_s[t];
            S0 *= e; S1 *= e; S2 *= e; S3 *= e;
            float k0 = k_s[t][lane], k1 = k_s[t][lane + 32];
            float k2 = k_s[t][lane + 64], k3 = k_s[t][lane + 96];
            float kv = fmaf(S3, k3, fmaf(S2, k2, fmaf(S1, k1, S0 * k0)));
#pragma unroll
            for (int off = 16; off; off >>= 1) kv += __shfl_xor_sync(0xffffffffu, kv, off);
            float delta = (v_s[t][w] - kv) * b_s[t];
            S0 = fmaf(k0, delta, S0);
            S1 = fmaf(k1, delta, S1);
            S2 = fmaf(k2, delta, S2);
            S3 = fmaf(k3, delta, S3);
            float q0 = q_s[t][lane], q1 = q_s[t][lane + 32];
            float q2 = q_s[t][lane + 64], q3 = q_s[t][lane + 96];
            float o = fmaf(S3, q3, fmaf(S2, q2, fmaf(S1, q1, S0 * q0)));
#pragma unroll
            for (int off = 16; off; off >>= 1) o += __shfl_xor_sync(0xffffffffu, o, off);
            if (lane == 0) o_s[t][w] = o;
        }
        __syncthreads();
        {
            int t = tid >> 3, j = tid & 7;
            g_core[(size_t)(t0 + t) * VALUE_DIM + hv * DV + dvb + j] = o_s[t][j];
        }
    }
}

// ================= RMS norm * silu(z) gating -> bf16 hi/lo for GEMM3 =================
__global__ void gate_kernel(const float* __restrict__ norm_weight) {
    int b = blockIdx.x;
    int l = b >> 5, hv = b & 31;
    int d = threadIdx.x;
    size_t ci = (size_t)l * VALUE_DIM + hv * DV + d;
    float c = g_core[ci];
    float s = c * c;
#pragma unroll
    for (int off = 16; off; off >>= 1) s += __shfl_xor_sync(0xffffffffu, s, off);
    __shared__ float sm[4];
    if ((d & 31) == 0) sm[d >> 5] = s;
    __syncthreads();
    s = sm[0] + sm[1] + sm[2] + sm[3];
    float scale = rsqrtf(s * (1.f / 128.f) + EPS);
    int hk = hv >> 1, r = hv & 1;
    float z = g_qkvz[(size_t)l * NQKVZ + hk * 768 + 512 + r * 128 + d];
    float sz = z / (1.f + expf(-z));
    float v = c * scale * norm_weight[d] * sz;
    __nv_bfloat16 h = __float2bfloat16(v);
    g_A3hi[ci] = h;
    g_A3lo[ci] = __float2bfloat16(v - __bfloat162float(h));
}

// ================= launch =================
extern "C" void kernel_launch(void* const* d_in, const int* in_sizes, int n_in,
                              void* d_out, int out_size) {
    const float* hs      = (const float*)d_in[0];
    const float* W_qkvz  = (const float*)d_in[1];
    const float* W_ba    = (const float*)d_in[2];
    const float* conv_w  = (const float*)d_in[3];
    const float* A_log   = (const float*)d_in[4];
    const float* dt_bias = (const float*)d_in[5];
    const float* norm_w  = (const float*)d_in[6];
    const float* W_out   = (const float*)d_in[7];
    float* out = (float*)d_out;

    // conversions
    split_hs<<<(L * HID) / 256, 256>>>(hs, L * HID);
    {
        dim3 g(NQKVZ / 32, HID / 32);
        transpose_split<<<g, dim3(32, 8)>>>(W_qkvz, HID, NQKVZ, 0);
    }
    {
        dim3 g(HID / 32, VALUE_DIM / 32);
        transpose_split<<<g, dim3(32, 8)>>>(W_out, VALUE_DIM, HID, 1);
    }

    // 1) qkvz = hs @ W_qkvz (HMMA bf16x3) -> g_qkvz
    {
        dim3 grid(NQKVZ / 128, L / 128);
        gemm3x<<<grid, 256>>>(0, nullptr, NQKVZ, HID);
    }
    // 2) ba = hs @ W_ba -> g_ba (fp32, tiny)
    {
        dim3 grid(1, L / 128);
        sgemm_ba<<<grid, 256>>>(hs, W_ba, L, 64, HID);
    }
    // 3) conv + silu
    conv_silu_kernel<<<(L * CONV_DIM) / 256, 256>>>(conv_w);
    // 4) q/k l2norm
    qknorm_kernel<<<L * HK, 128>>>();
    // 5) g, beta
    gbeta_kernel<<<(L * HV + 255) / 256, 256>>>(A_log, dt_bias);
    // 6) delta-rule scan
    scan_kernel<<<HV * (DV / 8), 256>>>();
    // 7) gate -> A3 splits
    gate_kernel<<<L * HV, 128>>>(norm_w);
    // 8) out = gated_core @ W_out (HMMA bf16x3)
    {
        dim3 grid(HID / 128, L / 128);
        gemm3x<<<grid, 256>>>(1, out, HID, VALUE_DIM);
    }
}